// round 15
// baseline (speedup 1.0000x reference)
#include <cuda_runtime.h>
#include <cuda_bf16.h>
#include <cstdint>
#include <cstddef>

// ---------------- problem constants ----------------
#define B_     256
#define T_     200
#define KDEP   5
#define EMB_   300
#define SMALLD 30
#define IN_DIM 360      // 300 + 30 + 30
#define IN0    390      // true K of GEMM0
#define MEM_   300
#define BT_    (B_*T_)  // 51200
#define SLD    400      // S1 row stride (390 valid, pads zero) = GEMM0 padded K (50*8)
#define HLD    304      // h / S2 row stride (300 valid, pads zero) = GEMM1 padded K (38*8)

// ---------------- static device scratch (zero-initialized, never freed) ----------------
__device__ __align__(16) float g_x[(size_t)BT_*IN_DIM + 64]; // x [BT,360]; reused as S2 [BT,304]
__device__ __align__(16) float g_S[(size_t)BT_*SLD   + 64];  // S1 [BT,400]; cols 390..399 stay 0
__device__ __align__(16) float g_h[(size_t)BT_*HLD   + 64];  // h  [BT,304]; cols 300..303 stay 0
__device__ float g_invden[BT_];
__device__ float g_maskpad[BT_];

// ---------------- f32x2 helpers (einsum path) ----------------
__device__ __forceinline__ void ffma2(unsigned long long& d,
                                      unsigned long long a, unsigned long long b) {
    asm("fma.rn.f32x2 %0, %1, %2, %0;" : "+l"(d) : "l"(a), "l"(b));
}
__device__ __forceinline__ unsigned long long dup2(float v) {
    unsigned long long d;
    asm("mov.b64 %0, {%1, %1};" : "=l"(d) : "r"(__float_as_uint(v)));
    return d;
}
__device__ __forceinline__ float2 unpack2(unsigned long long v) {
    float2 f;
    asm("mov.b64 {%0, %1}, %2;" : "=f"(f.x), "=f"(f.y) : "l"(v));
    return f;
}

// ---------------- tf32 helpers (mma path) ----------------
__device__ __forceinline__ float tf32_rna(float a) {
    float r;
    asm("cvt.rna.tf32.f32 %0, %1;" : "=f"(r) : "f"(a));
    return r;
}
__device__ __forceinline__ void mma8(float d[4], const uint32_t a[4], const uint32_t b[2]) {
    asm volatile(
        "mma.sync.aligned.m16n8k8.row.col.f32.tf32.tf32.f32 "
        "{%0,%1,%2,%3}, {%4,%5,%6,%7}, {%8,%9}, {%0,%1,%2,%3};"
        : "+f"(d[0]), "+f"(d[1]), "+f"(d[2]), "+f"(d[3])
        : "r"(a[0]), "r"(a[1]), "r"(a[2]), "r"(a[3]), "r"(b[0]), "r"(b[1]));
}

// ---------------- prep: embedding gathers + dep ragged sum ----------------
__global__ void prep_kernel(const int* __restrict__ words, const int* __restrict__ pos,
                            const int* __restrict__ ner, const int* __restrict__ dep_ids,
                            const int* __restrict__ dep_mask,
                            const float* __restrict__ word_emb, const float* __restrict__ pos_emb,
                            const float* __restrict__ ner_emb, const float* __restrict__ dep_emb)
{
    int warp = threadIdx.x >> 5, lane = threadIdx.x & 31;
    int i = blockIdx.x * 8 + warp;            // token index
    if (i >= BT_) return;

    const float* wrow = word_emb + (size_t)words[i] * EMB_;
    float* xrow = g_x + (size_t)i * IN_DIM;
    #pragma unroll
    for (int j = lane; j < EMB_; j += 32) xrow[j] = wrow[j];

    if (lane < SMALLD) {
        xrow[300 + lane] = pos_emb[pos[i] * SMALLD + lane];
        xrow[330 + lane] = ner_emb[ner[i] * SMALLD + lane];
        float s = 0.f; int cnt = 0;
        #pragma unroll
        for (int k = 0; k < KDEP; k++) {
            int m = dep_mask[i * KDEP + k];
            cnt += m;
            if (m) s += dep_emb[dep_ids[i * KDEP + k] * SMALLD + lane];
        }
        if (cnt == 0) s = dep_emb[lane];          // dep_emb[0]
        s += dep_emb[SMALLD + lane];              // + dep_emb[SELF_LOOP_ID=1]
        g_S[(size_t)i * SLD + IN_DIM + lane] = s; // cols 360..389
    }
}

// ---------------- denom (1/(rowsum+1)) + out_mask ----------------
__global__ void maskden_kernel(const int* __restrict__ adj, float* __restrict__ mask_out)
{
    __shared__ float rs_sh[T_];
    int b = blockIdx.x;
    int tid = threadIdx.x;                     // 256
    const int* Ab = adj + (size_t)b * T_ * T_;

    int col = 0;
    if (tid < T_) {
        for (int s = 0; s < T_; s++) col += Ab[s * T_ + tid];
    }
    int warp = tid >> 5, lane = tid & 31;
    for (int row = warp; row < T_; row += 8) {
        int acc = 0;
        for (int j = lane; j < T_; j += 32) acc += Ab[row * T_ + j];
        #pragma unroll
        for (int off = 16; off; off >>= 1) acc += __shfl_down_sync(0xffffffffu, acc, off);
        if (lane == 0) rs_sh[row] = (float)acc;
    }
    __syncthreads();
    if (tid < T_) {
        float rs = rs_sh[tid];
        g_invden[b * T_ + tid] = 1.0f / (rs + 1.0f);
        mask_out[b * T_ + tid] = ((rs + (float)col) == 0.0f) ? 1.0f : 0.0f;
    }
}

// ---------------- batched einsum: Out[b] = adj[b] @ X[b] + X[b]  (R13 config) ----------------
// 64x64 tile, BK=8, 256 threads, 4x4/thread via m-paired f32x2, double-buffered.
__global__ void __launch_bounds__(256) einsum_kernel(const int* __restrict__ adj,
                              const float* __restrict__ X, int ldx,
                              float* __restrict__ Out, int ldo, int Ncols, int padz)
{
    __shared__ __align__(16) float As[2][8][68];   // [k][m] (m contiguous), padded
    __shared__ __align__(16) float Bs[2][8][68];   // [k][n], padded
    const int b  = blockIdx.z;
    const int m0 = blockIdx.y * 64;
    const int n0 = blockIdx.x * 64;
    const int tid = threadIdx.x;
    const int tr = tid >> 4, tc = tid & 15;
    const int* Ab = adj + (size_t)b * (T_ * T_);
    const float* Xb = X + (size_t)b * T_ * ldx;

    float ra[2], rb[2];
    #pragma unroll
    for (int i = 0; i < 2; i++) {
        int slot = tid + i * 256;                // 64m x 8k
        int r = slot >> 3, c = slot & 7;
        ra[i] = (m0 + r < T_) ? (float)Ab[(m0 + r) * T_ + c] : 0.f;
    }
    #pragma unroll
    for (int i = 0; i < 2; i++) {
        int idx = tid + i * 256;                 // 8k x 64n
        int r = idx >> 6, c = idx & 63;
        rb[i] = (n0 + c < Ncols) ? Xb[r * ldx + n0 + c] : 0.f;
    }
    #pragma unroll
    for (int i = 0; i < 2; i++) { int s = tid + i*256; As[0][s & 7][s >> 3] = ra[i]; }
    #pragma unroll
    for (int i = 0; i < 2; i++) { int s = tid + i*256; Bs[0][s >> 6][s & 63] = rb[i]; }
    __syncthreads();

    unsigned long long accp[2][4] = {};
    const int NSTEP = T_ / 8;                    // 25
    for (int s = 0; s < NSTEP; s++) {
        int p = s & 1;
        if (s + 1 < NSTEP) {
            int k0 = (s + 1) * 8;
            #pragma unroll
            for (int i = 0; i < 2; i++) {
                int slot = tid + i * 256;
                int r = slot >> 3, c = slot & 7;
                ra[i] = (m0 + r < T_) ? (float)Ab[(m0 + r) * T_ + k0 + c] : 0.f;
            }
            #pragma unroll
            for (int i = 0; i < 2; i++) {
                int idx = tid + i * 256;
                int r = idx >> 6, c = idx & 63;
                rb[i] = (n0 + c < Ncols) ? Xb[(k0 + r) * ldx + n0 + c] : 0.f;
            }
        }
        #pragma unroll
        for (int kk = 0; kk < 8; kk++) {
            ulonglong2 ap = *reinterpret_cast<const ulonglong2*>(&As[p][kk][tr * 4]);
            float4 bv = *reinterpret_cast<const float4*>(&Bs[p][kk][tc * 4]);
            unsigned long long bd[4] = { dup2(bv.x), dup2(bv.y), dup2(bv.z), dup2(bv.w) };
            #pragma unroll
            for (int j = 0; j < 4; j++) { ffma2(accp[0][j], ap.x, bd[j]); }
            #pragma unroll
            for (int j = 0; j < 4; j++) { ffma2(accp[1][j], ap.y, bd[j]); }
        }
        if (s + 1 < NSTEP) {
            int q = 1 - p;
            #pragma unroll
            for (int i = 0; i < 2; i++) { int t = tid + i*256; As[q][t & 7][t >> 3] = ra[i]; }
            #pragma unroll
            for (int i = 0; i < 2; i++) { int t = tid + i*256; Bs[q][t >> 6][t & 63] = rb[i]; }
            __syncthreads();
        }
    }
    #pragma unroll
    for (int mi = 0; mi < 2; mi++) {
        #pragma unroll
        for (int half = 0; half < 2; half++) {
            int m = m0 + tr * 4 + 2 * mi + half;
            if (m >= T_) continue;
            #pragma unroll
            for (int j = 0; j < 4; j++) {
                float2 v = unpack2(accp[mi][j]);
                float a = half ? v.y : v.x;
                int n = n0 + tc * 4 + j;
                float* o = &Out[((size_t)b * T_ + m) * ldo + n];
                if (n < Ncols)     *o = a + Xb[m * ldx + n];
                else if (n < padz) *o = 0.f;
            }
        }
    }
}

// ---------------- tensor-core dense GEMM: C = relu((A@W + 2*bias) * invden) ----------------
// mma.sync m16n8k8 TF32, 3-MMA hi/lo split (error ~2^-21).
// CTA: 128m x 64n, 8 warps (4m x 2n), warp tile 32x32 (2 m-frags x 4 n-frags).
// BK=8, double-buffered smem with hi/lo planes. M % 128 == 0, A read guard-free
// (lda multiple of 8, pad cols zero). W guarded with true K, N.
__global__ void __launch_bounds__(256, 2) mma_gemm_kernel(
        const float* __restrict__ A, int lda, int nk,
        const float* __restrict__ W, int K, int N,
        const float* __restrict__ bias, const float* __restrict__ invden,
        float* __restrict__ C, int ldc)
{
    // strides chosen so (stride % 32) == 8 -> conflict-free frag LDS
    __shared__ float Ah[2][8][136], Al[2][8][136];
    __shared__ float Bh[2][8][72],  Bl[2][8][72];

    const int tid  = threadIdx.x;
    const int wid  = tid >> 5, lane = tid & 31;
    const int g    = lane >> 2, tig = lane & 3;
    const int m0   = blockIdx.y * 128;
    const int n0   = blockIdx.x * 64;
    const int wm   = (wid >> 1) * 32;      // warp m offset (4 warps)
    const int wn   = (wid & 1) * 32;       // warp n offset (2 warps)

    // fill lane mapping: A: m = (wid&3)*32 + lane, kq = wid>>2 (0/1) -> k = kq*4..+3
    const int fa_m  = ((wid & 3) << 5) + lane;
    const int fa_kq = wid >> 2;
    // B: n = tid & 63, rows r0 = tid>>6 and r0+4
    const int fb_n  = tid & 63;
    const int fb_r  = tid >> 6;

    float acc[2][4][4] = {};

    // ---- prologue: chunk 0 into buffer 0 ----
    {
        float4 va = *reinterpret_cast<const float4*>(&A[(size_t)(m0 + fa_m) * lda + fa_kq * 4]);
        float vh, vl;
        #pragma unroll
        for (int j = 0; j < 4; j++) {
            float v = (&va.x)[j];
            vh = tf32_rna(v); vl = tf32_rna(v - vh);
            Ah[0][fa_kq * 4 + j][fa_m] = vh;
            Al[0][fa_kq * 4 + j][fa_m] = vl;
        }
        #pragma unroll
        for (int i = 0; i < 2; i++) {
            int r = fb_r + i * 4;
            float v = (r < K && n0 + fb_n < N) ? W[(size_t)r * N + n0 + fb_n] : 0.f;
            vh = tf32_rna(v); vl = tf32_rna(v - vh);
            Bh[0][r][fb_n] = vh;
            Bl[0][r][fb_n] = vl;
        }
    }
    __syncthreads();

    for (int c = 0; c < nk; c++) {
        const int p = c & 1;
        float4 va; float vb[2];
        const bool more = (c + 1 < nk);
        if (more) {
            int k0 = (c + 1) * 8;
            va = *reinterpret_cast<const float4*>(&A[(size_t)(m0 + fa_m) * lda + k0 + fa_kq * 4]);
            #pragma unroll
            for (int i = 0; i < 2; i++) {
                int gk = k0 + fb_r + i * 4;
                vb[i] = (gk < K && n0 + fb_n < N) ? W[(size_t)gk * N + n0 + fb_n] : 0.f;
            }
        }

        // ---- fragment loads (conflict-free) ----
        uint32_t ah[2][4], al[2][4], bh[4][2], bl[4][2];
        #pragma unroll
        for (int mf = 0; mf < 2; mf++) {
            int mm = wm + mf * 16 + g;
            ah[mf][0] = __float_as_uint(Ah[p][tig    ][mm    ]);
            ah[mf][1] = __float_as_uint(Ah[p][tig    ][mm + 8]);
            ah[mf][2] = __float_as_uint(Ah[p][tig + 4][mm    ]);
            ah[mf][3] = __float_as_uint(Ah[p][tig + 4][mm + 8]);
            al[mf][0] = __float_as_uint(Al[p][tig    ][mm    ]);
            al[mf][1] = __float_as_uint(Al[p][tig    ][mm + 8]);
            al[mf][2] = __float_as_uint(Al[p][tig + 4][mm    ]);
            al[mf][3] = __float_as_uint(Al[p][tig + 4][mm + 8]);
        }
        #pragma unroll
        for (int nf = 0; nf < 4; nf++) {
            int nn = wn + nf * 8 + g;
            bh[nf][0] = __float_as_uint(Bh[p][tig    ][nn]);
            bh[nf][1] = __float_as_uint(Bh[p][tig + 4][nn]);
            bl[nf][0] = __float_as_uint(Bl[p][tig    ][nn]);
            bl[nf][1] = __float_as_uint(Bl[p][tig + 4][nn]);
        }
        // ---- 3-split MMAs ----
        #pragma unroll
        for (int mf = 0; mf < 2; mf++)
            #pragma unroll
            for (int nf = 0; nf < 4; nf++) {
                mma8(acc[mf][nf], ah[mf], bh[nf]);   // hi*hi
                mma8(acc[mf][nf], al[mf], bh[nf]);   // lo*hi
                mma8(acc[mf][nf], ah[mf], bl[nf]);   // hi*lo
            }

        if (more) {
            const int q = p ^ 1;
            float vh, vl;
            #pragma unroll
            for (int j = 0; j < 4; j++) {
                float v = (&va.x)[j];
                vh = tf32_rna(v); vl = tf32_rna(v - vh);
                Ah[q][fa_kq * 4 + j][fa_m] = vh;
                Al[q][fa_kq * 4 + j][fa_m] = vl;
            }
            #pragma unroll
            for (int i = 0; i < 2; i++) {
                int r = fb_r + i * 4;
                float v = vb[i];
                vh = tf32_rna(v); vl = tf32_rna(v - vh);
                Bh[q][r][fb_n] = vh;
                Bl[q][r][fb_n] = vl;
            }
            __syncthreads();
        }
    }

    // ---- epilogue: relu((acc + 2*bias) * invden) ----
    #pragma unroll
    for (int mf = 0; mf < 2; mf++) {
        int r0 = m0 + wm + mf * 16 + g;
        int r1 = r0 + 8;
        float i0 = invden[r0], i1 = invden[r1];
        #pragma unroll
        for (int nf = 0; nf < 4; nf++) {
            int col = n0 + wn + nf * 8 + 2 * tig;
            if (col >= N) continue;
            float b0 = 2.0f * bias[col];
            float v0 = fmaxf((acc[mf][nf][0] + b0) * i0, 0.f);
            float v2 = fmaxf((acc[mf][nf][2] + b0) * i1, 0.f);
            if (col + 1 < N) {
                float b1 = 2.0f * bias[col + 1];
                float v1 = fmaxf((acc[mf][nf][1] + b1) * i0, 0.f);
                float v3 = fmaxf((acc[mf][nf][3] + b1) * i1, 0.f);
                *reinterpret_cast<float2*>(&C[(size_t)r0 * ldc + col]) = make_float2(v0, v1);
                *reinterpret_cast<float2*>(&C[(size_t)r1 * ldc + col]) = make_float2(v2, v3);
            } else {
                C[(size_t)r0 * ldc + col] = v0;
                C[(size_t)r1 * ldc + col] = v2;
            }
        }
    }
}

// ---------------- launch ----------------
extern "C" void kernel_launch(void* const* d_in, const int* in_sizes, int n_in,
                              void* d_out, int out_size)
{
    const int* adj      = (const int*)d_in[0];
    const int* words    = (const int*)d_in[1];
    const int* pos      = (const int*)d_in[2];
    const int* ner      = (const int*)d_in[3];
    const int* dep_ids  = (const int*)d_in[4];
    const int* dep_mask = (const int*)d_in[5];
    int base = n_in - 8;                    // trailing 8 arrays are fixed
    const float* word_emb = (const float*)d_in[base + 0];
    const float* pos_emb  = (const float*)d_in[base + 1];
    const float* ner_emb  = (const float*)d_in[base + 2];
    const float* dep_emb  = (const float*)d_in[base + 3];
    const float* W0_w     = (const float*)d_in[base + 4];
    const float* W0_b     = (const float*)d_in[base + 5];
    const float* W1_w     = (const float*)d_in[base + 6];
    const float* W1_b     = (const float*)d_in[base + 7];

    float* out = (float*)d_out;

    void *px, *pS, *ph, *pinv, *pmaskpad;
    cudaGetSymbolAddress(&px, g_x);
    cudaGetSymbolAddress(&pS, g_S);
    cudaGetSymbolAddress(&ph, g_h);
    cudaGetSymbolAddress(&pinv, g_invden);
    cudaGetSymbolAddress(&pmaskpad, g_maskpad);
    float* gx   = (float*)px;
    float* gS   = (float*)pS;
    float* gh   = (float*)ph;
    float* ginv = (float*)pinv;

    float* mask_out = ((long long)out_size >= (long long)BT_ * MEM_ + BT_)
                        ? (out + (size_t)BT_ * MEM_) : (float*)pmaskpad;

    // 1) embeddings + dep columns of S1
    prep_kernel<<<BT_ / 8, 256>>>(words, pos, ner, dep_ids, dep_mask,
                                  word_emb, pos_emb, ner_emb, dep_emb);

    // 2) denom + out_mask
    maskden_kernel<<<B_, 256>>>(adj, mask_out);

    // 3) S1[:, :360] = A@x + x   (cols 360..389 from prep; 390..399 static zero)
    einsum_kernel<<<dim3(6, 4, B_), 256>>>(adj, gx, IN_DIM, gS, SLD, IN_DIM, IN_DIM);

    // 4) h = relu((S1 @ W0 + 2*b0) * invden)   K=390 padded to 400 (50 chunks of 8)
    mma_gemm_kernel<<<dim3(5, BT_ / 128), 256>>>(gS, SLD, 50, W0_w, IN0, MEM_,
                                                 W0_b, ginv, gh, HLD);

    // 5) S2 = A@h + h  (into g_x, stride 304; cols 300..303 zero-filled)
    einsum_kernel<<<dim3(5, 4, B_), 256>>>(adj, gh, HLD, gx, HLD, MEM_, HLD);

    // 6) out = relu((S2 @ W1 + 2*b1) * invden)  K=300 padded to 304 (38 chunks of 8)
    mma_gemm_kernel<<<dim3(5, BT_ / 128), 256>>>(gx, HLD, 38, W1_w, MEM_, MEM_,
                                                 W1_b, ginv, out, MEM_);
}

// round 16
// speedup vs baseline: 1.0436x; 1.0436x over previous
#include <cuda_runtime.h>
#include <cuda_bf16.h>
#include <cstdint>
#include <cstddef>

// ---------------- problem constants ----------------
#define B_     256
#define T_     200
#define KDEP   5
#define EMB_   300
#define SMALLD 30
#define IN_DIM 360      // 300 + 30 + 30
#define IN0    390      // true K of GEMM0
#define MEM_   300
#define BT_    (B_*T_)  // 51200
#define SLD    400      // S1 row stride (390 valid, zero pad) = GEMM0 K (25*16)
#define HLD    304      // h / S2 row stride (300 valid, zero pad) = GEMM1 K (19*16)
#define NPAD   320      // padded N for W planes (5 n-tiles of 64)

// ---------------- static device scratch (zero-initialized, never freed) ----------------
__device__ __align__(16) float g_x  [(size_t)BT_*IN_DIM + 64]; // x embeddings (einsum1 X)
__device__ __align__(16) float g_S1h[(size_t)BT_*SLD + 64];    // S1 hi plane
__device__ __align__(16) float g_S1l[(size_t)BT_*SLD + 64];    // S1 lo plane
__device__ __align__(16) float g_h  [(size_t)BT_*HLD + 64];    // layer-0 out (einsum2 X)
__device__ __align__(16) float g_S2h[(size_t)BT_*HLD + 64];    // S2 hi plane
__device__ __align__(16) float g_S2l[(size_t)BT_*HLD + 64];    // S2 lo plane
__device__ __align__(16) float g_W0h[SLD*NPAD], g_W0l[SLD*NPAD];
__device__ __align__(16) float g_W1h[HLD*NPAD], g_W1l[HLD*NPAD];
__device__ float g_invden[BT_];
__device__ float g_maskpad[BT_];

// ---------------- f32x2 helpers (einsum SIMT path) ----------------
__device__ __forceinline__ void ffma2(unsigned long long& d,
                                      unsigned long long a, unsigned long long b) {
    asm("fma.rn.f32x2 %0, %1, %2, %0;" : "+l"(d) : "l"(a), "l"(b));
}
__device__ __forceinline__ unsigned long long dup2(float v) {
    unsigned long long d;
    asm("mov.b64 %0, {%1, %1};" : "=l"(d) : "r"(__float_as_uint(v)));
    return d;
}
__device__ __forceinline__ float2 unpack2(unsigned long long v) {
    float2 f;
    asm("mov.b64 {%0, %1}, %2;" : "=f"(f.x), "=f"(f.y) : "l"(v));
    return f;
}

// ---------------- tf32 helpers (mma path) ----------------
__device__ __forceinline__ float tf32_rna(float a) {
    float r;
    asm("cvt.rna.tf32.f32 %0, %1;" : "=f"(r) : "f"(a));
    return r;
}
__device__ __forceinline__ void mma8(float d[4], const uint32_t a[4], const uint32_t b[2]) {
    asm volatile(
        "mma.sync.aligned.m16n8k8.row.col.f32.tf32.tf32.f32 "
        "{%0,%1,%2,%3}, {%4,%5,%6,%7}, {%8,%9}, {%0,%1,%2,%3};"
        : "+f"(d[0]), "+f"(d[1]), "+f"(d[2]), "+f"(d[3])
        : "r"(a[0]), "r"(a[1]), "r"(a[2]), "r"(a[3]), "r"(b[0]), "r"(b[1]));
}

// ---------------- W split: Wpad[k][n] = hi/lo(W[k][n]), zero padded ----------------
__global__ void wsplit_kernel(const float* __restrict__ W, int K, int N, int kp,
                              float* __restrict__ Wh, float* __restrict__ Wl)
{
    int idx = blockIdx.x * 256 + threadIdx.x;
    if (idx >= kp * NPAD) return;
    int k = idx / NPAD, n = idx % NPAD;
    float v = (k < K && n < N) ? W[(size_t)k * N + n] : 0.f;
    float hi = tf32_rna(v);
    Wh[idx] = hi;
    Wl[idx] = tf32_rna(v - hi);
}

// ---------------- prep: embedding gathers + dep ragged sum ----------------
__global__ void prep_kernel(const int* __restrict__ words, const int* __restrict__ pos,
                            const int* __restrict__ ner, const int* __restrict__ dep_ids,
                            const int* __restrict__ dep_mask,
                            const float* __restrict__ word_emb, const float* __restrict__ pos_emb,
                            const float* __restrict__ ner_emb, const float* __restrict__ dep_emb)
{
    int warp = threadIdx.x >> 5, lane = threadIdx.x & 31;
    int i = blockIdx.x * 8 + warp;            // token index
    if (i >= BT_) return;

    const float* wrow = word_emb + (size_t)words[i] * EMB_;
    float* xrow = g_x + (size_t)i * IN_DIM;
    #pragma unroll
    for (int j = lane; j < EMB_; j += 32) xrow[j] = wrow[j];

    if (lane < SMALLD) {
        xrow[300 + lane] = pos_emb[pos[i] * SMALLD + lane];
        xrow[330 + lane] = ner_emb[ner[i] * SMALLD + lane];
        float s = 0.f; int cnt = 0;
        #pragma unroll
        for (int k = 0; k < KDEP; k++) {
            int m = dep_mask[i * KDEP + k];
            cnt += m;
            if (m) s += dep_emb[dep_ids[i * KDEP + k] * SMALLD + lane];
        }
        if (cnt == 0) s = dep_emb[lane];          // dep_emb[0]
        s += dep_emb[SMALLD + lane];              // + dep_emb[SELF_LOOP_ID=1]
        float hi = tf32_rna(s);
        g_S1h[(size_t)i * SLD + IN_DIM + lane] = hi;
        g_S1l[(size_t)i * SLD + IN_DIM + lane] = tf32_rna(s - hi);
    }
}

// ---------------- denom (1/(rowsum+1)) + out_mask ----------------
__global__ void maskden_kernel(const int* __restrict__ adj, float* __restrict__ mask_out)
{
    __shared__ float rs_sh[T_];
    int b = blockIdx.x;
    int tid = threadIdx.x;                     // 256
    const int* Ab = adj + (size_t)b * T_ * T_;

    int col = 0;
    if (tid < T_) {
        for (int s = 0; s < T_; s++) col += Ab[s * T_ + tid];
    }
    int warp = tid >> 5, lane = tid & 31;
    for (int row = warp; row < T_; row += 8) {
        int acc = 0;
        for (int j = lane; j < T_; j += 32) acc += Ab[row * T_ + j];
        #pragma unroll
        for (int off = 16; off; off >>= 1) acc += __shfl_down_sync(0xffffffffu, acc, off);
        if (lane == 0) rs_sh[row] = (float)acc;
    }
    __syncthreads();
    if (tid < T_) {
        float rs = rs_sh[tid];
        g_invden[b * T_ + tid] = 1.0f / (rs + 1.0f);
        mask_out[b * T_ + tid] = ((rs + (float)col) == 0.0f) ? 1.0f : 0.0f;
    }
}

// ---------------- batched einsum: hi/lo(adj[b] @ X[b] + X[b]) -> planes ----------------
// 64x64 tile, BK=8, 256 threads, 4x4/thread via m-paired f32x2, double-buffered.
// Epilogue splits each value into tf32 hi/lo planes. Zero-fills [Ncols, padz).
__global__ void __launch_bounds__(256) einsum_kernel(const int* __restrict__ adj,
                              const float* __restrict__ X, int ldx,
                              float* __restrict__ Oh, float* __restrict__ Ol,
                              int ldo, int Ncols, int padz)
{
    __shared__ __align__(16) float As[2][8][68];   // [k][m] (m contiguous), padded
    __shared__ __align__(16) float Bs[2][8][68];   // [k][n], padded
    const int b  = blockIdx.z;
    const int m0 = blockIdx.y * 64;
    const int n0 = blockIdx.x * 64;
    const int tid = threadIdx.x;
    const int tr = tid >> 4, tc = tid & 15;
    const int* Ab = adj + (size_t)b * (T_ * T_);
    const float* Xb = X + (size_t)b * T_ * ldx;

    float ra[2], rb[2];
    #pragma unroll
    for (int i = 0; i < 2; i++) {
        int slot = tid + i * 256;                // 64m x 8k
        int r = slot >> 3, c = slot & 7;
        ra[i] = (m0 + r < T_) ? (float)Ab[(m0 + r) * T_ + c] : 0.f;
    }
    #pragma unroll
    for (int i = 0; i < 2; i++) {
        int idx = tid + i * 256;                 // 8k x 64n
        int r = idx >> 6, c = idx & 63;
        rb[i] = (n0 + c < Ncols) ? Xb[r * ldx + n0 + c] : 0.f;
    }
    #pragma unroll
    for (int i = 0; i < 2; i++) { int s = tid + i*256; As[0][s & 7][s >> 3] = ra[i]; }
    #pragma unroll
    for (int i = 0; i < 2; i++) { int s = tid + i*256; Bs[0][s >> 6][s & 63] = rb[i]; }
    __syncthreads();

    unsigned long long accp[2][4] = {};
    const int NSTEP = T_ / 8;                    // 25
    for (int s = 0; s < NSTEP; s++) {
        int p = s & 1;
        if (s + 1 < NSTEP) {
            int k0 = (s + 1) * 8;
            #pragma unroll
            for (int i = 0; i < 2; i++) {
                int slot = tid + i * 256;
                int r = slot >> 3, c = slot & 7;
                ra[i] = (m0 + r < T_) ? (float)Ab[(m0 + r) * T_ + k0 + c] : 0.f;
            }
            #pragma unroll
            for (int i = 0; i < 2; i++) {
                int idx = tid + i * 256;
                int r = idx >> 6, c = idx & 63;
                rb[i] = (n0 + c < Ncols) ? Xb[(k0 + r) * ldx + n0 + c] : 0.f;
            }
        }
        #pragma unroll
        for (int kk = 0; kk < 8; kk++) {
            ulonglong2 ap = *reinterpret_cast<const ulonglong2*>(&As[p][kk][tr * 4]);
            float4 bv = *reinterpret_cast<const float4*>(&Bs[p][kk][tc * 4]);
            unsigned long long bd[4] = { dup2(bv.x), dup2(bv.y), dup2(bv.z), dup2(bv.w) };
            #pragma unroll
            for (int j = 0; j < 4; j++) { ffma2(accp[0][j], ap.x, bd[j]); }
            #pragma unroll
            for (int j = 0; j < 4; j++) { ffma2(accp[1][j], ap.y, bd[j]); }
        }
        if (s + 1 < NSTEP) {
            int q = 1 - p;
            #pragma unroll
            for (int i = 0; i < 2; i++) { int t = tid + i*256; As[q][t & 7][t >> 3] = ra[i]; }
            #pragma unroll
            for (int i = 0; i < 2; i++) { int t = tid + i*256; Bs[q][t >> 6][t & 63] = rb[i]; }
            __syncthreads();
        }
    }
    #pragma unroll
    for (int mi = 0; mi < 2; mi++) {
        #pragma unroll
        for (int half = 0; half < 2; half++) {
            int m = m0 + tr * 4 + 2 * mi + half;
            if (m >= T_) continue;
            size_t rowoff = ((size_t)b * T_ + m) * ldo;
            #pragma unroll
            for (int j = 0; j < 4; j++) {
                float2 vv = unpack2(accp[mi][j]);
                float a = half ? vv.y : vv.x;
                int n = n0 + tc * 4 + j;
                if (n < Ncols) {
                    float v = a + Xb[m * ldx + n];
                    float hi = tf32_rna(v);
                    Oh[rowoff + n] = hi;
                    Ol[rowoff + n] = tf32_rna(v - hi);
                } else if (n < padz) {
                    Oh[rowoff + n] = 0.f;
                    Ol[rowoff + n] = 0.f;
                }
            }
        }
    }
}

// ---------------- tensor-core dense GEMM: C = relu((A@W + 2*bias) * invden) ----------------
// mma.sync m16n8k8 TF32, 3-term hi/lo split; all operands pre-split in gmem planes,
// so fills are pure guard-free float4 copies. CTA 128m x 64n, 8 warps (4m x 2n),
// warp 32x32 (2 m-frags x 4 n-frags), BK=16 double-buffered.
// lda multiple of 16 (pad cols zero); W planes padded [kp x NPAD] with zeros.
__global__ void __launch_bounds__(256, 2) mma_gemm_kernel(
        const float* __restrict__ Ahg, const float* __restrict__ Alg, int lda, int nch,
        const float* __restrict__ Whg, const float* __restrict__ Wlg,
        int N, const float* __restrict__ bias, const float* __restrict__ invden,
        float* __restrict__ C, int ldc)
{
    __shared__ float Ah[2][128][20], Al[2][128][20];   // [buf][m][k] stride 20
    __shared__ float Bh[2][16][72],  Bl[2][16][72];    // [buf][k][n] stride 72

    const int tid  = threadIdx.x;
    const int wid  = tid >> 5, lane = tid & 31;
    const int g    = lane >> 2, tig = lane & 3;
    const int m0   = blockIdx.y * 128;
    const int n0   = blockIdx.x * 64;
    const int wm   = (wid >> 1) * 32;      // warp m offset (4 warps)
    const int wn   = (wid & 1) * 32;       // warp n offset (2 warps)

    // fill lane mappings
    const int a_r0 = tid >> 2, a_cq = (tid & 3) * 4;          // A: slots tid, tid+256
    const int b_r  = tid >> 4, b_cq = (tid & 15) * 4;         // B: one slot

    float acc[2][4][4] = {};

    // ---- prologue: chunk 0 into buffer 0 ----
    {
        #pragma unroll
        for (int i = 0; i < 2; i++) {
            int r = a_r0 + i * 64;
            size_t goff = (size_t)(m0 + r) * lda + a_cq;
            *reinterpret_cast<float4*>(&Ah[0][r][a_cq]) =
                *reinterpret_cast<const float4*>(&Ahg[goff]);
            *reinterpret_cast<float4*>(&Al[0][r][a_cq]) =
                *reinterpret_cast<const float4*>(&Alg[goff]);
        }
        size_t woff = (size_t)b_r * NPAD + n0 + b_cq;
        *reinterpret_cast<float4*>(&Bh[0][b_r][b_cq]) =
            *reinterpret_cast<const float4*>(&Whg[woff]);
        *reinterpret_cast<float4*>(&Bl[0][b_r][b_cq]) =
            *reinterpret_cast<const float4*>(&Wlg[woff]);
    }
    __syncthreads();

    for (int c = 0; c < nch; c++) {
        const int p = c & 1;
        const bool more = (c + 1 < nch);
        float4 pah[2], pal[2], pbh, pbl;
        if (more) {
            int k0 = (c + 1) * 16;
            #pragma unroll
            for (int i = 0; i < 2; i++) {
                int r = a_r0 + i * 64;
                size_t goff = (size_t)(m0 + r) * lda + k0 + a_cq;
                pah[i] = *reinterpret_cast<const float4*>(&Ahg[goff]);
                pal[i] = *reinterpret_cast<const float4*>(&Alg[goff]);
            }
            size_t woff = (size_t)(k0 + b_r) * NPAD + n0 + b_cq;
            pbh = *reinterpret_cast<const float4*>(&Whg[woff]);
            pbl = *reinterpret_cast<const float4*>(&Wlg[woff]);
        }

        // ---- 2 k-steps of fragment loads + 3-term MMAs ----
        #pragma unroll
        for (int ks = 0; ks < 2; ks++) {
            const int ko = ks * 8;
            uint32_t ah[2][4], al[2][4], bh[4][2], bl[4][2];
            #pragma unroll
            for (int mf = 0; mf < 2; mf++) {
                int mm = wm + mf * 16 + g;
                ah[mf][0] = __float_as_uint(Ah[p][mm    ][ko + tig    ]);
                ah[mf][1] = __float_as_uint(Ah[p][mm + 8][ko + tig    ]);
                ah[mf][2] = __float_as_uint(Ah[p][mm    ][ko + tig + 4]);
                ah[mf][3] = __float_as_uint(Ah[p][mm + 8][ko + tig + 4]);
                al[mf][0] = __float_as_uint(Al[p][mm    ][ko + tig    ]);
                al[mf][1] = __float_as_uint(Al[p][mm + 8][ko + tig    ]);
                al[mf][2] = __float_as_uint(Al[p][mm    ][ko + tig + 4]);
                al[mf][3] = __float_as_uint(Al[p][mm + 8][ko + tig + 4]);
            }
            #pragma unroll
            for (int nf = 0; nf < 4; nf++) {
                int nn = wn + nf * 8 + g;
                bh[nf][0] = __float_as_uint(Bh[p][ko + tig    ][nn]);
                bh[nf][1] = __float_as_uint(Bh[p][ko + tig + 4][nn]);
                bl[nf][0] = __float_as_uint(Bl[p][ko + tig    ][nn]);
                bl[nf][1] = __float_as_uint(Bl[p][ko + tig + 4][nn]);
            }
            #pragma unroll
            for (int mf = 0; mf < 2; mf++)
                #pragma unroll
                for (int nf = 0; nf < 4; nf++) {
                    mma8(acc[mf][nf], ah[mf], bh[nf]);   // hi*hi
                    mma8(acc[mf][nf], al[mf], bh[nf]);   // lo*hi
                    mma8(acc[mf][nf], ah[mf], bl[nf]);   // hi*lo
                }
        }

        if (more) {
            const int q = p ^ 1;
            #pragma unroll
            for (int i = 0; i < 2; i++) {
                int r = a_r0 + i * 64;
                *reinterpret_cast<float4*>(&Ah[q][r][a_cq]) = pah[i];
                *reinterpret_cast<float4*>(&Al[q][r][a_cq]) = pal[i];
            }
            *reinterpret_cast<float4*>(&Bh[q][b_r][b_cq]) = pbh;
            *reinterpret_cast<float4*>(&Bl[q][b_r][b_cq]) = pbl;
            __syncthreads();
        }
    }

    // ---- epilogue: relu((acc + 2*bias) * invden) ----
    #pragma unroll
    for (int mf = 0; mf < 2; mf++) {
        int r0 = m0 + wm + mf * 16 + g;
        int r1 = r0 + 8;
        float i0 = invden[r0], i1 = invden[r1];
        #pragma unroll
        for (int nf = 0; nf < 4; nf++) {
            int col = n0 + wn + nf * 8 + 2 * tig;
            if (col >= N) continue;
            float b0 = 2.0f * bias[col];
            float v0 = fmaxf((acc[mf][nf][0] + b0) * i0, 0.f);
            float v2 = fmaxf((acc[mf][nf][2] + b0) * i1, 0.f);
            if (col + 1 < N) {
                float b1 = 2.0f * bias[col + 1];
                float v1 = fmaxf((acc[mf][nf][1] + b1) * i0, 0.f);
                float v3 = fmaxf((acc[mf][nf][3] + b1) * i1, 0.f);
                *reinterpret_cast<float2*>(&C[(size_t)r0 * ldc + col]) = make_float2(v0, v1);
                *reinterpret_cast<float2*>(&C[(size_t)r1 * ldc + col]) = make_float2(v2, v3);
            } else {
                C[(size_t)r0 * ldc + col] = v0;
                C[(size_t)r1 * ldc + col] = v2;
            }
        }
    }
}

// ---------------- launch ----------------
extern "C" void kernel_launch(void* const* d_in, const int* in_sizes, int n_in,
                              void* d_out, int out_size)
{
    const int* adj      = (const int*)d_in[0];
    const int* words    = (const int*)d_in[1];
    const int* pos      = (const int*)d_in[2];
    const int* ner      = (const int*)d_in[3];
    const int* dep_ids  = (const int*)d_in[4];
    const int* dep_mask = (const int*)d_in[5];
    int base = n_in - 8;                    // trailing 8 arrays are fixed
    const float* word_emb = (const float*)d_in[base + 0];
    const float* pos_emb  = (const float*)d_in[base + 1];
    const float* ner_emb  = (const float*)d_in[base + 2];
    const float* dep_emb  = (const float*)d_in[base + 3];
    const float* W0_w     = (const float*)d_in[base + 4];
    const float* W0_b     = (const float*)d_in[base + 5];
    const float* W1_w     = (const float*)d_in[base + 6];
    const float* W1_b     = (const float*)d_in[base + 7];

    float* out = (float*)d_out;

    void *px, *ps1h, *ps1l, *ph, *ps2h, *ps2l, *pinv, *pmask;
    void *pw0h, *pw0l, *pw1h, *pw1l;
    cudaGetSymbolAddress(&px,   g_x);
    cudaGetSymbolAddress(&ps1h, g_S1h);
    cudaGetSymbolAddress(&ps1l, g_S1l);
    cudaGetSymbolAddress(&ph,   g_h);
    cudaGetSymbolAddress(&ps2h, g_S2h);
    cudaGetSymbolAddress(&ps2l, g_S2l);
    cudaGetSymbolAddress(&pinv, g_invden);
    cudaGetSymbolAddress(&pmask, g_maskpad);
    cudaGetSymbolAddress(&pw0h, g_W0h);
    cudaGetSymbolAddress(&pw0l, g_W0l);
    cudaGetSymbolAddress(&pw1h, g_W1h);
    cudaGetSymbolAddress(&pw1l, g_W1l);
    float* gx   = (float*)px;
    float* gh   = (float*)ph;
    float* ginv = (float*)pinv;

    float* mask_out = ((long long)out_size >= (long long)BT_ * MEM_ + BT_)
                        ? (out + (size_t)BT_ * MEM_) : (float*)pmask;

    // 0) W hi/lo splits into padded planes (tiny)
    wsplit_kernel<<<(SLD * NPAD + 255) / 256, 256>>>(W0_w, IN0, MEM_, SLD,
                                                     (float*)pw0h, (float*)pw0l);
    wsplit_kernel<<<(HLD * NPAD + 255) / 256, 256>>>(W1_w, MEM_, MEM_, HLD,
                                                     (float*)pw1h, (float*)pw1l);

    // 1) embeddings + dep columns (split) of S1
    prep_kernel<<<BT_ / 8, 256>>>(words, pos, ner, dep_ids, dep_mask,
                                  word_emb, pos_emb, ner_emb, dep_emb);

    // 2) denom + out_mask
    maskden_kernel<<<B_, 256>>>(adj, mask_out);

    // 3) S1[:, :360] = split(A@x + x)   (cols 360..389 from prep; 390..399 static zero)
    einsum_kernel<<<dim3(6, 4, B_), 256>>>(adj, gx, IN_DIM,
                                           (float*)ps1h, (float*)ps1l, SLD, IN_DIM, IN_DIM);

    // 4) h = relu((S1 @ W0 + 2*b0) * invden)   K=400 -> 25 chunks of 16
    mma_gemm_kernel<<<dim3(5, BT_ / 128), 256>>>((float*)ps1h, (float*)ps1l, SLD, 25,
                                                 (float*)pw0h, (float*)pw0l,
                                                 MEM_, W0_b, ginv, gh, HLD);

    // 5) S2 = split(A@h + h)  (stride 304; cols 300..303 zero-filled)
    einsum_kernel<<<dim3(5, 4, B_), 256>>>(adj, gh, HLD,
                                           (float*)ps2h, (float*)ps2l, HLD, MEM_, HLD);

    // 6) out = relu((S2 @ W1 + 2*b1) * invden)  K=304 -> 19 chunks of 16
    mma_gemm_kernel<<<dim3(5, BT_ / 128), 256>>>((float*)ps2h, (float*)ps2l, HLD, 19,
                                                 (float*)pw1h, (float*)pw1l,
                                                 MEM_, W1_b, ginv, out, MEM_);
}

// round 17
// speedup vs baseline: 1.0699x; 1.0252x over previous
#include <cuda_runtime.h>
#include <cuda_bf16.h>
#include <cstdint>
#include <cstddef>

// ---------------- problem constants ----------------
#define B_     256
#define T_     200
#define KDEP   5
#define EMB_   300
#define SMALLD 30
#define IN_DIM 360      // 300 + 30 + 30
#define IN0    390      // true K of GEMM0
#define MEM_   300
#define BT_    (B_*T_)  // 51200
#define SLD    400      // S1 row stride (390 valid, zero pad) = GEMM0 K (25*16)
#define HLD    304      // h / S2 row stride (300 valid, zero pad) = GEMM1 K (19*16)
#define NPAD   320      // padded N for W planes (5 n-tiles of 64)

// ---------------- static device scratch (zero-initialized, never freed) ----------------
__device__ __align__(16) float g_x  [(size_t)BT_*IN_DIM + 64]; // x embeddings (einsum1 X)
__device__ __align__(16) float g_S1h[(size_t)BT_*SLD + 64];    // S1 hi plane
__device__ __align__(16) float g_S1l[(size_t)BT_*SLD + 64];    // S1 lo plane
__device__ __align__(16) float g_h  [(size_t)BT_*HLD + 64];    // layer-0 out (einsum2 X)
__device__ __align__(16) float g_S2h[(size_t)BT_*HLD + 64];    // S2 hi plane
__device__ __align__(16) float g_S2l[(size_t)BT_*HLD + 64];    // S2 lo plane
__device__ __align__(16) float g_W0h[SLD*NPAD], g_W0l[SLD*NPAD];
__device__ __align__(16) float g_W1h[HLD*NPAD], g_W1l[HLD*NPAD];
__device__ float g_invden[BT_];
__device__ float g_maskpad[BT_];

// ---------------- tf32 helpers ----------------
__device__ __forceinline__ float tf32_rna(float a) {
    float r;
    asm("cvt.rna.tf32.f32 %0, %1;" : "=f"(r) : "f"(a));
    return r;
}
__device__ __forceinline__ void mma8(float d[4], const uint32_t a[4], const uint32_t b[2]) {
    asm volatile(
        "mma.sync.aligned.m16n8k8.row.col.f32.tf32.tf32.f32 "
        "{%0,%1,%2,%3}, {%4,%5,%6,%7}, {%8,%9}, {%0,%1,%2,%3};"
        : "+f"(d[0]), "+f"(d[1]), "+f"(d[2]), "+f"(d[3])
        : "r"(a[0]), "r"(a[1]), "r"(a[2]), "r"(a[3]), "r"(b[0]), "r"(b[1]));
}

// ---------------- W split: Wpad[k][n] = hi/lo(W[k][n]), zero padded ----------------
__global__ void wsplit_kernel(const float* __restrict__ W, int K, int N, int kp,
                              float* __restrict__ Wh, float* __restrict__ Wl)
{
    int idx = blockIdx.x * 256 + threadIdx.x;
    if (idx >= kp * NPAD) return;
    int k = idx / NPAD, n = idx % NPAD;
    float v = (k < K && n < N) ? W[(size_t)k * N + n] : 0.f;
    float hi = tf32_rna(v);
    Wh[idx] = hi;
    Wl[idx] = tf32_rna(v - hi);
}

// ---------------- prep: embedding gathers + dep ragged sum ----------------
__global__ void prep_kernel(const int* __restrict__ words, const int* __restrict__ pos,
                            const int* __restrict__ ner, const int* __restrict__ dep_ids,
                            const int* __restrict__ dep_mask,
                            const float* __restrict__ word_emb, const float* __restrict__ pos_emb,
                            const float* __restrict__ ner_emb, const float* __restrict__ dep_emb)
{
    int warp = threadIdx.x >> 5, lane = threadIdx.x & 31;
    int i = blockIdx.x * 8 + warp;            // token index
    if (i >= BT_) return;

    const float* wrow = word_emb + (size_t)words[i] * EMB_;
    float* xrow = g_x + (size_t)i * IN_DIM;
    #pragma unroll
    for (int j = lane; j < EMB_; j += 32) xrow[j] = wrow[j];

    if (lane < SMALLD) {
        xrow[300 + lane] = pos_emb[pos[i] * SMALLD + lane];
        xrow[330 + lane] = ner_emb[ner[i] * SMALLD + lane];
        float s = 0.f; int cnt = 0;
        #pragma unroll
        for (int k = 0; k < KDEP; k++) {
            int m = dep_mask[i * KDEP + k];
            cnt += m;
            if (m) s += dep_emb[dep_ids[i * KDEP + k] * SMALLD + lane];
        }
        if (cnt == 0) s = dep_emb[lane];          // dep_emb[0]
        s += dep_emb[SMALLD + lane];              // + dep_emb[SELF_LOOP_ID=1]
        float hi = tf32_rna(s);
        g_S1h[(size_t)i * SLD + IN_DIM + lane] = hi;
        g_S1l[(size_t)i * SLD + IN_DIM + lane] = tf32_rna(s - hi);
    }
}

// ---------------- denom (1/(rowsum+1)) + out_mask ----------------
__global__ void maskden_kernel(const int* __restrict__ adj, float* __restrict__ mask_out)
{
    __shared__ float rs_sh[T_];
    int b = blockIdx.x;
    int tid = threadIdx.x;                     // 256
    const int* Ab = adj + (size_t)b * T_ * T_;

    int col = 0;
    if (tid < T_) {
        for (int s = 0; s < T_; s++) col += Ab[s * T_ + tid];
    }
    int warp = tid >> 5, lane = tid & 31;
    for (int row = warp; row < T_; row += 8) {
        int acc = 0;
        for (int j = lane; j < T_; j += 32) acc += Ab[row * T_ + j];
        #pragma unroll
        for (int off = 16; off; off >>= 1) acc += __shfl_down_sync(0xffffffffu, acc, off);
        if (lane == 0) rs_sh[row] = (float)acc;
    }
    __syncthreads();
    if (tid < T_) {
        float rs = rs_sh[tid];
        g_invden[b * T_ + tid] = 1.0f / (rs + 1.0f);
        mask_out[b * T_ + tid] = ((rs + (float)col) == 0.0f) ? 1.0f : 0.0f;
    }
}

// ---------------- tensor-core einsum: hi/lo(adj[b] @ X[b] + X[b]) -> planes ----------------
// adj is {0,1} -> exact in tf32 -> 2-term split (A@Xhi + A@Xlo).
// CTA 64m x 64n, 4 warps (2m x 2n), warp 32x32 (2 m-frags x 4 n-frags), BK=16
// double-buffered. K=200 padded to 208 (13 chunks). m-tiles {0,64,128,136}:
// tile 3 overlaps rows 136..191 of tile 2 with bit-identical values (benign).
__global__ void __launch_bounds__(128, 4) einsum_mma_kernel(
        const int* __restrict__ adj, const float* __restrict__ X, int ldx,
        float* __restrict__ Oh, float* __restrict__ Ol, int ldo, int Ncols)
{
    __shared__ float As[2][64][20];                // [buf][m][k], exact adj
    __shared__ float Xh[2][16][72], Xl[2][16][72]; // [buf][k][n]

    const int b  = blockIdx.z;
    const int m0 = (blockIdx.y == 3) ? 136 : blockIdx.y * 64;
    const int n0 = blockIdx.x * 64;
    const int tid = threadIdx.x;
    const int wid = tid >> 5, lane = tid & 31;
    const int g = lane >> 2, tig = lane & 3;
    const int wm = (wid >> 1) * 32;                // 2 warps in m
    const int wn = (wid & 1) * 32;                 // 2 warps in n
    const int* Ab = adj + (size_t)b * (T_ * T_);
    const float* Xb = X + (size_t)b * T_ * ldx;

    // fill lane mappings
    const int a_m = tid >> 1;                      // 0..63
    const int a_k = (tid & 1) * 8;                 // 0 or 8
    const int x_r = tid >> 4;                      // 0..7 (+8 on 2nd iter)
    const int x_n = (tid & 15) * 4;                // 0..60

    float acc[2][4][4] = {};
    const int NCH = 13;                            // 208 = 13*16

    // ---- prologue: chunk 0 -> buffer 0 ----
    {
        #pragma unroll
        for (int j = 0; j < 8; j++) {
            int k = a_k + j;
            As[0][a_m][k] = (float)Ab[(m0 + a_m) * T_ + k];   // k<16 < 200 always
        }
        #pragma unroll
        for (int i = 0; i < 2; i++) {
            int r = x_r + i * 8;                   // < 16 < 200
            float4 v;
            if (n0 + x_n + 3 < Ncols) {
                v = *reinterpret_cast<const float4*>(&Xb[(size_t)r * ldx + n0 + x_n]);
            } else {
                v = make_float4(0.f, 0.f, 0.f, 0.f);
                if (n0 + x_n + 0 < Ncols) v.x = Xb[(size_t)r * ldx + n0 + x_n + 0];
                if (n0 + x_n + 1 < Ncols) v.y = Xb[(size_t)r * ldx + n0 + x_n + 1];
                if (n0 + x_n + 2 < Ncols) v.z = Xb[(size_t)r * ldx + n0 + x_n + 2];
            }
            float hh;
            hh = tf32_rna(v.x); Xh[0][r][x_n+0] = hh; Xl[0][r][x_n+0] = tf32_rna(v.x - hh);
            hh = tf32_rna(v.y); Xh[0][r][x_n+1] = hh; Xl[0][r][x_n+1] = tf32_rna(v.y - hh);
            hh = tf32_rna(v.z); Xh[0][r][x_n+2] = hh; Xl[0][r][x_n+2] = tf32_rna(v.z - hh);
            hh = tf32_rna(v.w); Xh[0][r][x_n+3] = hh; Xl[0][r][x_n+3] = tf32_rna(v.w - hh);
        }
    }
    __syncthreads();

    for (int c = 0; c < NCH; c++) {
        const int p = c & 1;
        const bool more = (c + 1 < NCH);
        float pa[8]; float4 px[2];
        if (more) {
            int k0 = (c + 1) * 16;
            #pragma unroll
            for (int j = 0; j < 8; j++) {
                int k = k0 + a_k + j;
                pa[j] = (k < T_) ? (float)Ab[(m0 + a_m) * T_ + k] : 0.f;
            }
            #pragma unroll
            for (int i = 0; i < 2; i++) {
                int r = x_r + i * 8, gk = k0 + r;
                float4 v = make_float4(0.f, 0.f, 0.f, 0.f);
                if (gk < T_) {
                    if (n0 + x_n + 3 < Ncols) {
                        v = *reinterpret_cast<const float4*>(&Xb[(size_t)gk * ldx + n0 + x_n]);
                    } else {
                        if (n0 + x_n + 0 < Ncols) v.x = Xb[(size_t)gk * ldx + n0 + x_n + 0];
                        if (n0 + x_n + 1 < Ncols) v.y = Xb[(size_t)gk * ldx + n0 + x_n + 1];
                        if (n0 + x_n + 2 < Ncols) v.z = Xb[(size_t)gk * ldx + n0 + x_n + 2];
                    }
                }
                px[i] = v;
            }
        }

        // ---- 2 k-steps: fragment loads + 2-term MMAs ----
        #pragma unroll
        for (int ks = 0; ks < 2; ks++) {
            const int ko = ks * 8;
            uint32_t af[2][4], xh[4][2], xl[4][2];
            #pragma unroll
            for (int mf = 0; mf < 2; mf++) {
                int mm = wm + mf * 16 + g;
                af[mf][0] = __float_as_uint(As[p][mm    ][ko + tig    ]);
                af[mf][1] = __float_as_uint(As[p][mm + 8][ko + tig    ]);
                af[mf][2] = __float_as_uint(As[p][mm    ][ko + tig + 4]);
                af[mf][3] = __float_as_uint(As[p][mm + 8][ko + tig + 4]);
            }
            #pragma unroll
            for (int nf = 0; nf < 4; nf++) {
                int nn = wn + nf * 8 + g;
                xh[nf][0] = __float_as_uint(Xh[p][ko + tig    ][nn]);
                xh[nf][1] = __float_as_uint(Xh[p][ko + tig + 4][nn]);
                xl[nf][0] = __float_as_uint(Xl[p][ko + tig    ][nn]);
                xl[nf][1] = __float_as_uint(Xl[p][ko + tig + 4][nn]);
            }
            #pragma unroll
            for (int mf = 0; mf < 2; mf++)
                #pragma unroll
                for (int nf = 0; nf < 4; nf++) {
                    mma8(acc[mf][nf], af[mf], xh[nf]);
                    mma8(acc[mf][nf], af[mf], xl[nf]);
                }
        }

        if (more) {
            const int q = p ^ 1;
            #pragma unroll
            for (int j = 0; j < 8; j++) As[q][a_m][a_k + j] = pa[j];
            #pragma unroll
            for (int i = 0; i < 2; i++) {
                int r = x_r + i * 8;
                float hh;
                hh = tf32_rna(px[i].x); Xh[q][r][x_n+0] = hh; Xl[q][r][x_n+0] = tf32_rna(px[i].x - hh);
                hh = tf32_rna(px[i].y); Xh[q][r][x_n+1] = hh; Xl[q][r][x_n+1] = tf32_rna(px[i].y - hh);
                hh = tf32_rna(px[i].z); Xh[q][r][x_n+2] = hh; Xl[q][r][x_n+2] = tf32_rna(px[i].z - hh);
                hh = tf32_rna(px[i].w); Xh[q][r][x_n+3] = hh; Xl[q][r][x_n+3] = tf32_rna(px[i].w - hh);
            }
            __syncthreads();
        }
    }

    // ---- epilogue: v = acc + X (exact fp32 x); split hi/lo; store planes ----
    #pragma unroll
    for (int mf = 0; mf < 2; mf++) {
        int r0 = m0 + wm + mf * 16 + g;
        int r1 = r0 + 8;
        const float* x0 = &Xb[(size_t)r0 * ldx];
        const float* x1 = &Xb[(size_t)r1 * ldx];
        size_t o0 = ((size_t)b * T_ + r0) * ldo;
        size_t o1 = ((size_t)b * T_ + r1) * ldo;
        #pragma unroll
        for (int nf = 0; nf < 4; nf++) {
            int col = n0 + wn + nf * 8 + 2 * tig;
            #pragma unroll
            for (int cc = 0; cc < 2; cc++) {
                int n = col + cc;
                if (n >= Ncols) continue;
                float v0 = acc[mf][nf][cc]     + x0[n];
                float v1 = acc[mf][nf][2 + cc] + x1[n];
                float h0 = tf32_rna(v0), h1 = tf32_rna(v1);
                Oh[o0 + n] = h0; Ol[o0 + n] = tf32_rna(v0 - h0);
                Oh[o1 + n] = h1; Ol[o1 + n] = tf32_rna(v1 - h1);
            }
        }
    }
}

// ---------------- tensor-core dense GEMM: C = relu((A@W + 2*bias) * invden) ----------------
// (unchanged from R16 — passed at rel_err 4.2e-6)
__global__ void __launch_bounds__(256, 2) mma_gemm_kernel(
        const float* __restrict__ Ahg, const float* __restrict__ Alg, int lda, int nch,
        const float* __restrict__ Whg, const float* __restrict__ Wlg,
        int N, const float* __restrict__ bias, const float* __restrict__ invden,
        float* __restrict__ C, int ldc)
{
    __shared__ float Ah[2][128][20], Al[2][128][20];   // [buf][m][k] stride 20
    __shared__ float Bh[2][16][72],  Bl[2][16][72];    // [buf][k][n] stride 72

    const int tid  = threadIdx.x;
    const int wid  = tid >> 5, lane = tid & 31;
    const int g    = lane >> 2, tig = lane & 3;
    const int m0   = blockIdx.y * 128;
    const int n0   = blockIdx.x * 64;
    const int wm   = (wid >> 1) * 32;      // warp m offset (4 warps)
    const int wn   = (wid & 1) * 32;       // warp n offset (2 warps)

    const int a_r0 = tid >> 2, a_cq = (tid & 3) * 4;
    const int b_r  = tid >> 4, b_cq = (tid & 15) * 4;

    float acc[2][4][4] = {};

    {
        #pragma unroll
        for (int i = 0; i < 2; i++) {
            int r = a_r0 + i * 64;
            size_t goff = (size_t)(m0 + r) * lda + a_cq;
            *reinterpret_cast<float4*>(&Ah[0][r][a_cq]) =
                *reinterpret_cast<const float4*>(&Ahg[goff]);
            *reinterpret_cast<float4*>(&Al[0][r][a_cq]) =
                *reinterpret_cast<const float4*>(&Alg[goff]);
        }
        size_t woff = (size_t)b_r * NPAD + n0 + b_cq;
        *reinterpret_cast<float4*>(&Bh[0][b_r][b_cq]) =
            *reinterpret_cast<const float4*>(&Whg[woff]);
        *reinterpret_cast<float4*>(&Bl[0][b_r][b_cq]) =
            *reinterpret_cast<const float4*>(&Wlg[woff]);
    }
    __syncthreads();

    for (int c = 0; c < nch; c++) {
        const int p = c & 1;
        const bool more = (c + 1 < nch);
        float4 pah[2], pal[2], pbh, pbl;
        if (more) {
            int k0 = (c + 1) * 16;
            #pragma unroll
            for (int i = 0; i < 2; i++) {
                int r = a_r0 + i * 64;
                size_t goff = (size_t)(m0 + r) * lda + k0 + a_cq;
                pah[i] = *reinterpret_cast<const float4*>(&Ahg[goff]);
                pal[i] = *reinterpret_cast<const float4*>(&Alg[goff]);
            }
            size_t woff = (size_t)(k0 + b_r) * NPAD + n0 + b_cq;
            pbh = *reinterpret_cast<const float4*>(&Whg[woff]);
            pbl = *reinterpret_cast<const float4*>(&Wlg[woff]);
        }

        #pragma unroll
        for (int ks = 0; ks < 2; ks++) {
            const int ko = ks * 8;
            uint32_t ah[2][4], al[2][4], bh[4][2], bl[4][2];
            #pragma unroll
            for (int mf = 0; mf < 2; mf++) {
                int mm = wm + mf * 16 + g;
                ah[mf][0] = __float_as_uint(Ah[p][mm    ][ko + tig    ]);
                ah[mf][1] = __float_as_uint(Ah[p][mm + 8][ko + tig    ]);
                ah[mf][2] = __float_as_uint(Ah[p][mm    ][ko + tig + 4]);
                ah[mf][3] = __float_as_uint(Ah[p][mm + 8][ko + tig + 4]);
                al[mf][0] = __float_as_uint(Al[p][mm    ][ko + tig    ]);
                al[mf][1] = __float_as_uint(Al[p][mm + 8][ko + tig    ]);
                al[mf][2] = __float_as_uint(Al[p][mm    ][ko + tig + 4]);
                al[mf][3] = __float_as_uint(Al[p][mm + 8][ko + tig + 4]);
            }
            #pragma unroll
            for (int nf = 0; nf < 4; nf++) {
                int nn = wn + nf * 8 + g;
                bh[nf][0] = __float_as_uint(Bh[p][ko + tig    ][nn]);
                bh[nf][1] = __float_as_uint(Bh[p][ko + tig + 4][nn]);
                bl[nf][0] = __float_as_uint(Bl[p][ko + tig    ][nn]);
                bl[nf][1] = __float_as_uint(Bl[p][ko + tig + 4][nn]);
            }
            #pragma unroll
            for (int mf = 0; mf < 2; mf++)
                #pragma unroll
                for (int nf = 0; nf < 4; nf++) {
                    mma8(acc[mf][nf], ah[mf], bh[nf]);
                    mma8(acc[mf][nf], al[mf], bh[nf]);
                    mma8(acc[mf][nf], ah[mf], bl[nf]);
                }
        }

        if (more) {
            const int q = p ^ 1;
            #pragma unroll
            for (int i = 0; i < 2; i++) {
                int r = a_r0 + i * 64;
                *reinterpret_cast<float4*>(&Ah[q][r][a_cq]) = pah[i];
                *reinterpret_cast<float4*>(&Al[q][r][a_cq]) = pal[i];
            }
            *reinterpret_cast<float4*>(&Bh[q][b_r][b_cq]) = pbh;
            *reinterpret_cast<float4*>(&Bl[q][b_r][b_cq]) = pbl;
            __syncthreads();
        }
    }

    #pragma unroll
    for (int mf = 0; mf < 2; mf++) {
        int r0 = m0 + wm + mf * 16 + g;
        int r1 = r0 + 8;
        float i0 = invden[r0], i1 = invden[r1];
        #pragma unroll
        for (int nf = 0; nf < 4; nf++) {
            int col = n0 + wn + nf * 8 + 2 * tig;
            if (col >= N) continue;
            float b0 = 2.0f * bias[col];
            float v0 = fmaxf((acc[mf][nf][0] + b0) * i0, 0.f);
            float v2 = fmaxf((acc[mf][nf][2] + b0) * i1, 0.f);
            if (col + 1 < N) {
                float b1 = 2.0f * bias[col + 1];
                float v1 = fmaxf((acc[mf][nf][1] + b1) * i0, 0.f);
                float v3 = fmaxf((acc[mf][nf][3] + b1) * i1, 0.f);
                *reinterpret_cast<float2*>(&C[(size_t)r0 * ldc + col]) = make_float2(v0, v1);
                *reinterpret_cast<float2*>(&C[(size_t)r1 * ldc + col]) = make_float2(v2, v3);
            } else {
                C[(size_t)r0 * ldc + col] = v0;
                C[(size_t)r1 * ldc + col] = v2;
            }
        }
    }
}

// ---------------- launch ----------------
extern "C" void kernel_launch(void* const* d_in, const int* in_sizes, int n_in,
                              void* d_out, int out_size)
{
    const int* adj      = (const int*)d_in[0];
    const int* words    = (const int*)d_in[1];
    const int* pos      = (const int*)d_in[2];
    const int* ner      = (const int*)d_in[3];
    const int* dep_ids  = (const int*)d_in[4];
    const int* dep_mask = (const int*)d_in[5];
    int base = n_in - 8;                    // trailing 8 arrays are fixed
    const float* word_emb = (const float*)d_in[base + 0];
    const float* pos_emb  = (const float*)d_in[base + 1];
    const float* ner_emb  = (const float*)d_in[base + 2];
    const float* dep_emb  = (const float*)d_in[base + 3];
    const float* W0_w     = (const float*)d_in[base + 4];
    const float* W0_b     = (const float*)d_in[base + 5];
    const float* W1_w     = (const float*)d_in[base + 6];
    const float* W1_b     = (const float*)d_in[base + 7];

    float* out = (float*)d_out;

    void *px, *ps1h, *ps1l, *ph, *ps2h, *ps2l, *pinv, *pmask;
    void *pw0h, *pw0l, *pw1h, *pw1l;
    cudaGetSymbolAddress(&px,   g_x);
    cudaGetSymbolAddress(&ps1h, g_S1h);
    cudaGetSymbolAddress(&ps1l, g_S1l);
    cudaGetSymbolAddress(&ph,   g_h);
    cudaGetSymbolAddress(&ps2h, g_S2h);
    cudaGetSymbolAddress(&ps2l, g_S2l);
    cudaGetSymbolAddress(&pinv, g_invden);
    cudaGetSymbolAddress(&pmask, g_maskpad);
    cudaGetSymbolAddress(&pw0h, g_W0h);
    cudaGetSymbolAddress(&pw0l, g_W0l);
    cudaGetSymbolAddress(&pw1h, g_W1h);
    cudaGetSymbolAddress(&pw1l, g_W1l);
    float* gx   = (float*)px;
    float* gh   = (float*)ph;
    float* ginv = (float*)pinv;

    float* mask_out = ((long long)out_size >= (long long)BT_ * MEM_ + BT_)
                        ? (out + (size_t)BT_ * MEM_) : (float*)pmask;

    // 0) W hi/lo splits into padded planes (tiny)
    wsplit_kernel<<<(SLD * NPAD + 255) / 256, 256>>>(W0_w, IN0, MEM_, SLD,
                                                     (float*)pw0h, (float*)pw0l);
    wsplit_kernel<<<(HLD * NPAD + 255) / 256, 256>>>(W1_w, MEM_, MEM_, HLD,
                                                     (float*)pw1h, (float*)pw1l);

    // 1) embeddings + dep columns (split) of S1
    prep_kernel<<<BT_ / 8, 256>>>(words, pos, ner, dep_ids, dep_mask,
                                  word_emb, pos_emb, ner_emb, dep_emb);

    // 2) denom + out_mask
    maskden_kernel<<<B_, 256>>>(adj, mask_out);

    // 3) S1[:, :360] = split(A@x + x)   (cols 360..389 from prep; 390..399 static zero)
    einsum_mma_kernel<<<dim3(6, 4, B_), 128>>>(adj, gx, IN_DIM,
                                               (float*)ps1h, (float*)ps1l, SLD, IN_DIM);

    // 4) h = relu((S1 @ W0 + 2*b0) * invden)   K=400 -> 25 chunks of 16
    mma_gemm_kernel<<<dim3(5, BT_ / 128), 256>>>((float*)ps1h, (float*)ps1l, SLD, 25,
                                                 (float*)pw0h, (float*)pw0l,
                                                 MEM_, W0_b, ginv, gh, HLD);

    // 5) S2 = split(A@h + h)  (stride 304; cols 300..303 static zero)
    einsum_mma_kernel<<<dim3(5, 4, B_), 128>>>(adj, gh, HLD,
                                               (float*)ps2h, (float*)ps2l, HLD, MEM_);

    // 6) out = relu((S2 @ W1 + 2*b1) * invden)  K=304 -> 19 chunks of 16
    mma_gemm_kernel<<<dim3(5, BT_ / 128), 256>>>((float*)ps2h, (float*)ps2l, HLD, 19,
                                                 (float*)pw1h, (float*)pw1l,
                                                 MEM_, W1_b, ginv, out, MEM_);
}